// round 16
// baseline (speedup 1.0000x reference)
#include <cuda_runtime.h>
#include <cuda_fp16.h>
#include <cstdint>

// EvroModel: x[131072,256] -> relu(x@w1+b1)[.,64] -> tanh(@w2+b2)[.,16] -> @w3+b3 [.,4]
// -> softmax over the ENTIRE flattened tensor.
//
// Round 16: occupancy attack. fp16 2-way-split GEMM (R11 math) with
//  - warp tile 16x32 (c=16 regs) -> ~56 regs/thread -> __launch_bounds__(512,2)
//    -> 2 CTAs/SM resident (32 warps/SM, occ 25%->50%)
//  - CTA = 128 rows (16 warps: 8 m-tiles x 2 n-halves), NBLK=1024, smem 105KB
//  - tail on tid<128; separate 1-block reduce + lean scale kernels.

#define B_ROWS   131072
#define ROWS_CTA 128
#define NBLK     (B_ROWS / ROWS_CTA)   // 1024
#define TPB      512
#define KDIM     256
#define H1_PITCH 68

// float offsets in dynamic smem
#define SB_OFF_F   0                   // packed B frags: 16384 u32 (65536 B)
#define H1_OFF_F   16384               // 128 x 68 floats = 34816 B
#define W2_OFF_F   25088               // 64 x 16
#define B1_OFF_F   26112               // 64
#define B2_OFF_F   26176               // 16
#define W3_OFF_F   26192               // 16 x 4
#define B3_OFF_F   26256               // 4
#define RED_OFF_F  26260               // 16
#define SM_FLOATS  26276               // 105104 B -> 2 CTAs/SM fit (227KB)

__device__ float g_partials[NBLK];
__device__ float g_inv_sum;

__device__ __forceinline__ uint32_t smem_u32(const void* p) {
    uint32_t a;
    asm("{ .reg .u64 t; cvta.to.shared.u64 t, %1; cvt.u32.u64 %0, t; }" : "=r"(a) : "l"(p));
    return a;
}
__device__ __forceinline__ uint32_t pack_f16x2(float lo, float hi) {
    uint32_t d;
    asm("cvt.rn.f16x2.f32 %0, %1, %2;" : "=r"(d) : "f"(hi), "f"(lo));
    return d;
}
__device__ __forceinline__ void unpack_f16x2(uint32_t h, float& lo, float& hi) {
    asm("{ .reg .f16 x, y; mov.b32 {x, y}, %2; cvt.f32.f16 %0, x; cvt.f32.f16 %1, y; }"
        : "=f"(lo), "=f"(hi) : "r"(h));
}
__device__ __forceinline__ void split_pair(float lo, float hi, uint32_t& h, uint32_t& l) {
    h = pack_f16x2(lo, hi);
    float hlo, hhi;
    unpack_f16x2(h, hlo, hhi);
    l = pack_f16x2(lo - hlo, hi - hhi);
}
__device__ __forceinline__ void lds128(uint32_t r[4], uint32_t addr) {
    asm volatile("ld.shared.v4.b32 {%0,%1,%2,%3}, [%4];"
                 : "=r"(r[0]), "=r"(r[1]), "=r"(r[2]), "=r"(r[3]) : "r"(addr));
}
__device__ __forceinline__ void mma_f16(float c[4], const uint32_t a[4],
                                        uint32_t b0, uint32_t b1) {
    asm("mma.sync.aligned.m16n8k16.row.col.f32.f16.f16.f32 "
        "{%0,%1,%2,%3}, {%4,%5,%6,%7}, {%8,%9}, {%0,%1,%2,%3};"
        : "+f"(c[0]), "+f"(c[1]), "+f"(c[2]), "+f"(c[3])
        : "r"(a[0]), "r"(a[1]), "r"(a[2]), "r"(a[3]), "r"(b0), "r"(b1));
}

__global__ __launch_bounds__(TPB, 2)
void mlp_kernel(const float* __restrict__ x,
                const float* __restrict__ w1, const float* __restrict__ b1,
                const float* __restrict__ w2, const float* __restrict__ b2,
                const float* __restrict__ w3, const float* __restrict__ b3,
                float* __restrict__ out)
{
    extern __shared__ float sm[];
    char* smc = (char*)sm;
    float* sh1 = sm + H1_OFF_F;

    const int tid = threadIdx.x;
    const int wid = tid >> 5;
    const int lane = tid & 31;
    const int g = lane >> 2;       // 0..7
    const int tig = lane & 3;      // 0..3
    const int mt8 = wid & 7;       // m-tile (16 rows)
    const int nh = wid >> 3;       // n-half (4 nt)

    // ---- stage w1 as packed 2-level fp16 B-fragments (R11 layout) ----
    for (int e = tid; e < 16384; e += TPB) {
        int k = e >> 6, n = e & 63;
        float v = w1[e];
        __half hb = __float2half_rn(v);
        float hf = __half2float(hb);
        __half lb = __float2half_rn(v - hf);
        int b = k >> 4, cc = k & 15, t = cc >> 2, j = cc & 3;
        int nt = n >> 3, gg = n & 7;
        int q = (t + gg) & 3;
        uint32_t cell = (uint32_t)(((b * 8 + nt) * 8 + gg) * 4 + q);
        uint32_t sub = (uint32_t)((j >> 1) * 4 + (j & 1) * 2);
        *(__half*)(smc + cell * 16 + sub)     = hb;
        *(__half*)(smc + cell * 16 + 8 + sub) = lb;
    }
    {
        float* sw2 = sm + W2_OFF_F;
        for (int i = tid; i < 1024; i += TPB) sw2[i] = w2[i];
        if (tid < 64) sm[B1_OFF_F + tid] = b1[tid];
        if (tid < 16) sm[B2_OFF_F + tid] = b2[tid];
        if (tid < 64) sm[W3_OFF_F + tid] = w3[tid];
        if (tid < 4)  sm[B3_OFF_F + tid] = b3[tid];
    }
    __syncthreads();

    const uint32_t smb = smem_u32(sm);
    // fold the warp's n-half into the base address
    const uint32_t b_base = smb + (uint32_t)(nh * 2048 + (g * 4 + ((tig + g) & 3)) * 16);

    // ---- layer-1 GEMM: warp computes 16 rows x 32 cols ----
    const float* xb = x + ((size_t)blockIdx.x * ROWS_CTA + mt8 * 16 + g) * KDIM + tig * 4;

    float c[4][4];
    #pragma unroll
    for (int n = 0; n < 4; n++)
        #pragma unroll
        for (int r = 0; r < 4; r++) c[n][r] = 0.0f;

    float4 r0 = __ldg((const float4*)xb);
    float4 r1 = __ldg((const float4*)(xb + 8 * KDIM));

    #pragma unroll 1
    for (int kt = 0; kt < 16; kt++) {
        // split current A (rows g, g+8) into 2 fp16 levels
        uint32_t ah[4], al[4];
        split_pair(r0.x, r0.y, ah[0], al[0]);
        split_pair(r1.x, r1.y, ah[1], al[1]);
        split_pair(r0.z, r0.w, ah[2], al[2]);
        split_pair(r1.z, r1.w, ah[3], al[3]);

        // prefetch next kt's A
        if (kt < 15) {
            r0 = __ldg((const float4*)(xb + (kt + 1) * 16));
            r1 = __ldg((const float4*)(xb + 8 * KDIM + (kt + 1) * 16));
        }

        const uint32_t kt_base = b_base + (uint32_t)(kt * 4096);
        #pragma unroll
        for (int ntp = 0; ntp < 2; ntp++) {
            const int n0 = 2 * ntp, n1 = 2 * ntp + 1;
            uint32_t v0[4], v1[4];
            lds128(v0, kt_base + (uint32_t)(n0 * 512));   // [h_b0,h_b1,l_b0,l_b1]
            lds128(v1, kt_base + (uint32_t)(n1 * 512));
            // hh
            mma_f16(c[n0], ah, v0[0], v0[1]);
            mma_f16(c[n1], ah, v1[0], v1[1]);
            // hl
            mma_f16(c[n0], ah, v0[2], v0[3]);
            mma_f16(c[n1], ah, v1[2], v1[3]);
            // lh
            mma_f16(c[n0], al, v0[0], v0[1]);
            mma_f16(c[n1], al, v1[0], v1[1]);
        }
    }

    // ---- frags -> h1 ----
    #pragma unroll
    for (int j = 0; j < 4; j++) {
        int row0 = mt8 * 16 + g;
        int col = nh * 32 + j * 8 + tig * 2;
        float2 v0f; v0f.x = c[j][0]; v0f.y = c[j][1];
        float2 v1f; v1f.x = c[j][2]; v1f.y = c[j][3];
        *(float2*)&sh1[row0 * H1_PITCH + col] = v0f;
        *(float2*)&sh1[(row0 + 8) * H1_PITCH + col] = v1f;
    }
    __syncthreads();

    // ---- per-thread fp32 tail: rows 0..127 on tid<128 ----
    float s = 0.0f;
    if (tid < ROWS_CTA) {
        const float* sb1 = sm + B1_OFF_F;
        const float* sw2 = sm + W2_OFF_F;
        const float* sb2 = sm + B2_OFF_F;
        const float* sw3 = sm + W3_OFF_F;
        const float* sb3 = sm + B3_OFF_F;
        const float* hrow = &sh1[tid * H1_PITCH];

        float h2[16];
        #pragma unroll
        for (int j = 0; j < 16; j++) h2[j] = sb2[j];
        #pragma unroll
        for (int i4 = 0; i4 < 16; i4++) {
            float4 hv = *(const float4*)&hrow[i4 * 4];
            float h0 = fmaxf(hv.x + sb1[i4 * 4 + 0], 0.0f);
            float h1v = fmaxf(hv.y + sb1[i4 * 4 + 1], 0.0f);
            float h2v = fmaxf(hv.z + sb1[i4 * 4 + 2], 0.0f);
            float h3 = fmaxf(hv.w + sb1[i4 * 4 + 3], 0.0f);
            const float* wr0 = &sw2[(i4 * 4 + 0) * 16];
            const float* wr1 = &sw2[(i4 * 4 + 1) * 16];
            const float* wr2 = &sw2[(i4 * 4 + 2) * 16];
            const float* wr3 = &sw2[(i4 * 4 + 3) * 16];
            #pragma unroll
            for (int j = 0; j < 16; j++) {
                float t = fmaf(h0, wr0[j], h2[j]);
                t = fmaf(h1v, wr1[j], t);
                t = fmaf(h2v, wr2[j], t);
                h2[j] = fmaf(h3, wr3[j], t);
            }
        }
        #pragma unroll
        for (int j = 0; j < 16; j++) h2[j] = tanhf(h2[j]);

        float lg[4];
        #pragma unroll
        for (int j = 0; j < 4; j++) lg[j] = sb3[j];
        #pragma unroll
        for (int i = 0; i < 16; i++) {
            float h = h2[i];
            const float* wr = &sw3[i * 4];
            #pragma unroll
            for (int j = 0; j < 4; j++) lg[j] = fmaf(h, wr[j], lg[j]);
        }

        float e0 = __expf(lg[0]);
        float e1 = __expf(lg[1]);
        float e2 = __expf(lg[2]);
        float e3 = __expf(lg[3]);

        const size_t row = (size_t)blockIdx.x * ROWS_CTA + tid;
        float4 ev; ev.x = e0; ev.y = e1; ev.z = e2; ev.w = e3;
        ((float4*)out)[row] = ev;

        s = (e0 + e1) + (e2 + e3);
    }

    // deterministic reduction: shuffle within warps 0..3, then thread 0
    #pragma unroll
    for (int o = 16; o > 0; o >>= 1) s += __shfl_xor_sync(0xffffffffu, s, o);
    float* red = sm + RED_OFF_F;
    if (lane == 0 && wid < 4) red[wid] = s;
    __syncthreads();
    if (tid == 0) g_partials[blockIdx.x] = ((red[0] + red[1]) + (red[2] + red[3]));
}

// 1 block: deterministic reduction of 1024 partials -> g_inv_sum
__global__ void reduce_kernel()
{
    __shared__ float red[256];
    const int tid = threadIdx.x;   // 256
    float s = 0.0f;
    #pragma unroll
    for (int i = 0; i < 4; i++) s += g_partials[tid * 4 + i];
    red[tid] = s;
    __syncthreads();
    #pragma unroll
    for (int off = 128; off > 0; off >>= 1) {
        if (tid < off) red[tid] += red[tid + off];
        __syncthreads();
    }
    if (tid == 0) g_inv_sum = 1.0f / red[0];
}

// 256 blocks x 512 threads: one float4 each, scaled by the broadcast inverse.
__global__ void scale_kernel(float* __restrict__ out)
{
    const float inv = g_inv_sum;
    const int i = blockIdx.x * 512 + threadIdx.x;
    float4 v = ((float4*)out)[i];
    v.x *= inv; v.y *= inv; v.z *= inv; v.w *= inv;
    ((float4*)out)[i] = v;
}

extern "C" void kernel_launch(void* const* d_in, const int* in_sizes, int n_in,
                              void* d_out, int out_size)
{
    const float* x  = (const float*)d_in[0];
    const float* w1 = (const float*)d_in[1];
    const float* b1 = (const float*)d_in[2];
    const float* w2 = (const float*)d_in[3];
    const float* b2 = (const float*)d_in[4];
    const float* w3 = (const float*)d_in[5];
    const float* b3 = (const float*)d_in[6];
    float* out = (float*)d_out;

    const size_t smem = SM_FLOATS * sizeof(float);
    cudaFuncSetAttribute(mlp_kernel, cudaFuncAttributeMaxDynamicSharedMemorySize, (int)smem);

    mlp_kernel<<<NBLK, TPB, smem>>>(x, w1, b1, w2, b2, w3, b3, out);
    reduce_kernel<<<1, 256>>>();
    scale_kernel<<<256, 512>>>(out);
}